// round 8
// baseline (speedup 1.0000x reference)
#include <cuda_runtime.h>

#define NN 100000
#define MM 1000
#define KA 11     // A rank terms (k=0 of original folded into B slot 0)
#define KB 12     // B per m: [0]=c0*z0 (acc init), [1..11] pair with A[0..10]
#define TPB 256
#define VN 4      // n per thread (float4 store)
#define MT 10     // m tiles -> grid = 98*10 = 980 blocks (R4 geometry: best measured)
#define MC_MAX 100

typedef unsigned long long u64;

__device__ __forceinline__ u64 pack2(float lo, float hi) {
    u64 r; asm("mov.b64 %0, {%1,%2};" : "=l"(r) : "f"(lo), "f"(hi)); return r;
}
__device__ __forceinline__ void unpack2(u64 v, float& lo, float& hi) {
    asm("mov.b64 {%0,%1}, %2;" : "=f"(lo), "=f"(hi) : "l"(v));
}
__device__ __forceinline__ u64 fma2(u64 a, u64 b, u64 c) {
    u64 d; asm("fma.rn.f32x2 %0, %1, %2, %3;" : "=l"(d) : "l"(a), "l"(b), "l"(c)); return d;
}
__device__ __forceinline__ float fast_sin(float x)  { float r; asm("sin.approx.f32 %0, %1;"  : "=f"(r) : "f"(x)); return r; }
__device__ __forceinline__ float fast_cos(float x)  { float r; asm("cos.approx.f32 %0, %1;"  : "=f"(r) : "f"(x)); return r; }
__device__ __forceinline__ float fast_tanh(float x) { float r; asm("tanh.approx.f32 %0, %1;" : "=f"(r) : "f"(x)); return r; }

// Fused rank-12 outer product (R4 geometry + pipelinable __stcs stores):
//   out[m*NN + n] = c0*z0[m] + sum_{k=0..10} A[n,k] * B[m,k+1]
__global__ void __launch_bounds__(TPB, 4)
fused_kernel(const float* __restrict__ phi, const float* __restrict__ POD,
             const float* __restrict__ c, const float* __restrict__ omega,
             const float* __restrict__ z, const float* __restrict__ zsin,
             const float* __restrict__ zcos, const float* __restrict__ ztanh,
             const float* __restrict__ sc, const float* __restrict__ cc,
             const float* __restrict__ tc,
             float* __restrict__ out_final, float* __restrict__ out_latent,
             float* __restrict__ out_z) {
    __shared__ __align__(16) u64 Bs[MC_MAX * KB];  // B rows, dup'd into both f32x2 lanes

    const int tid = threadIdx.x;
    const int mBase = blockIdx.y * MC_MAX;                  // y in [0,10); MC*MT == MM exactly

    // ---- B tile: threads 0..MC_MAX-1 compute one m row each ----
    if (tid < MC_MAX) {
        int m = mBase + tid;
        u64* b = Bs + tid * KB;
        float bz0 = c[0] * z[m];
        b[0] = pack2(bz0, bz0);
#pragma unroll
        for (int t = 1; t < 6; t++) {
            float v = z[t * MM + m];
            b[t] = pack2(v, v);
        }
        float v6  = sc[0] * zsin[m];        b[6]  = pack2(v6, v6);
        float v7  = sc[1] * zsin[MM + m];   b[7]  = pack2(v7, v7);
        float v8  = cc[0] * zcos[m];        b[8]  = pack2(v8, v8);
        float v9  = cc[1] * zcos[MM + m];   b[9]  = pack2(v9, v9);
        float v10 = tc[0] * ztanh[m];       b[10] = pack2(v10, v10);
        float v11 = tc[1] * ztanh[MM + m];  b[11] = pack2(v11, v11);
    }

    // ---- z_values copy (once, by block (0,0)) ----
    if (blockIdx.x == 0 && blockIdx.y == 0) {
        for (int i = tid; i < 6 * MM; i += TPB) out_z[i] = z[i];
    }
    __syncthreads();

    const int n0 = (blockIdx.x * TPB + tid) * VN;
    if (n0 >= NN) return;  // NN % 4 == 0; in-range threads write full float4

    // ---- A features inline for this thread's 4 n's ----
    float4 p0 = *(const float4*)(phi + n0);
    float4 p1 = *(const float4*)(phi + NN + n0);
    float4 qa = *(const float4*)(POD + 2 * n0);
    float4 qb = *(const float4*)(POD + 2 * n0 + 4);

    float y0[4], y1[4];
    y0[0] = p0.x * qa.x;  y1[0] = p1.x * qa.y;
    y0[1] = p0.y * qa.z;  y1[1] = p1.y * qa.w;
    y0[2] = p0.z * qb.x;  y1[2] = p1.z * qb.y;
    y0[3] = p0.w * qb.z;  y1[3] = p1.w * qb.w;

    if (blockIdx.y == 0) {  // latent_spatial (N,2): [y0, y1] interleaved
        *(float4*)(out_latent + 2 * n0)     = make_float4(y0[0], y1[0], y0[1], y1[1]);
        *(float4*)(out_latent + 2 * n0 + 4) = make_float4(y0[2], y1[2], y0[3], y1[3]);
    }

    float c1 = c[1], c2 = c[2], c3 = c[3], c4 = c[4], c5 = c[5];
    float w0 = omega[0], w1 = omega[1], w2 = omega[2];
    float w3 = omega[3], w4 = omega[4], w5 = omega[5];

    // Pack A features directly as f32x2 pairs (n0/n1 lane, n2/n3 lane).
    u64 pa01[KA], pa23[KA];
#define PACK_K(k, EXPR)                                                      \
    pa01[k] = pack2(EXPR(0), EXPR(1));                                       \
    pa23[k] = pack2(EXPR(2), EXPR(3));
#define F0(j)  (c1 * y0[j])
#define F1(j)  (c2 * y1[j])
#define F2(j)  (c3 * y0[j] * y0[j])
#define F3(j)  (c4 * y0[j] * y1[j])
#define F4(j)  (c5 * y1[j] * y1[j])
#define F5(j)  fast_sin(w0 * y0[j])
#define F6(j)  fast_sin(w3 * y1[j])
#define F7(j)  fast_cos(w1 * y0[j])
#define F8(j)  fast_cos(w4 * y1[j])
#define F9(j)  fast_tanh(w2 * y0[j])
#define F10(j) fast_tanh(w5 * y1[j])
    PACK_K(0, F0)  PACK_K(1, F1)  PACK_K(2, F2)  PACK_K(3, F3)
    PACK_K(4, F4)  PACK_K(5, F5)  PACK_K(6, F6)  PACK_K(7, F7)
    PACK_K(8, F8)  PACK_K(9, F9)  PACK_K(10, F10)

    // ---- main store stream ----
    // __stcs (no asm memory clobber) lets the compiler hoist next-iteration
    // shared loads above this iteration's store and pipeline the loop.
    float* outBase = out_final + (size_t)mBase * NN + n0;
#pragma unroll 4
    for (int mi = 0; mi < MC_MAX; ++mi) {
        const ulonglong2* bb = (const ulonglong2*)(Bs + mi * KB);  // 6x LDS.128 (broadcast)
        ulonglong2 b01 = bb[0];
        u64 acc01 = fma2(pa01[0], b01.y, b01.x);   // init = c0*z0[m]
        u64 acc23 = fma2(pa23[0], b01.y, b01.x);
#pragma unroll
        for (int kk = 1; kk < 6; kk++) {
            ulonglong2 b = bb[kk];          // B slots 2kk, 2kk+1 -> A rows 2kk-1, 2kk
            acc01 = fma2(pa01[2 * kk - 1], b.x, acc01);
            acc23 = fma2(pa23[2 * kk - 1], b.x, acc23);
            acc01 = fma2(pa01[2 * kk],     b.y, acc01);
            acc23 = fma2(pa23[2 * kk],     b.y, acc23);
        }
        float4 o;
        unpack2(acc01, o.x, o.y);
        unpack2(acc23, o.z, o.w);
        __stcs((float4*)(outBase + (size_t)mi * NN), o);
    }
}

extern "C" void kernel_launch(void* const* d_in, const int* in_sizes, int n_in,
                              void* d_out, int out_size) {
    // Input order: X, phi, POD_modes, c_coef, z_values, zsin, zcos,
    //              ztanh, sin_coef, cos_coef, tanh_coef, omega
    const float* phi   = (const float*)d_in[1];
    const float* POD   = (const float*)d_in[2];
    const float* c     = (const float*)d_in[3];
    const float* z     = (const float*)d_in[4];
    const float* zsin  = (const float*)d_in[5];
    const float* zcos  = (const float*)d_in[6];
    const float* ztanh = (const float*)d_in[7];
    const float* sc    = (const float*)d_in[8];
    const float* cc    = (const float*)d_in[9];
    const float* tc    = (const float*)d_in[10];
    const float* omega = (const float*)d_in[11];

    float* out        = (float*)d_out;
    float* out_final  = out;                              // (M, N)
    float* out_latent = out + (size_t)MM * NN;            // (N, 2)
    float* out_z      = out_latent + (size_t)NN * 2;      // (6, M)

    dim3 grid((NN + TPB * VN - 1) / (TPB * VN), MT);      // (98, 10) = 980 blocks
    fused_kernel<<<grid, TPB>>>(phi, POD, c, omega, z, zsin, zcos, ztanh,
                                sc, cc, tc, out_final, out_latent, out_z);
}

// round 10
// speedup vs baseline: 1.0185x; 1.0185x over previous
#include <cuda_runtime.h>

#define NN 100000
#define MM 1000
#define KA 11     // A rank terms (k=0 of original folded into B slot 0)
#define KB 12     // B floats per m: [0]=c0*z0 (acc init), [1..11] pair with A[0..10]
#define TPB 256
#define VN 4      // n per thread (float4 store)
#define MT 10     // m tiles -> grid = 98*10 = 980 blocks (best-measured geometry)
#define MC_MAX 100

typedef unsigned long long u64;

__device__ __forceinline__ u64 pack2(float lo, float hi) {
    u64 r; asm("mov.b64 %0, {%1,%2};" : "=l"(r) : "f"(lo), "f"(hi)); return r;
}
__device__ __forceinline__ u64 dup2(float v) {
    u64 r; asm("mov.b64 %0, {%1,%1};" : "=l"(r) : "f"(v)); return r;
}
__device__ __forceinline__ void unpack2(u64 v, float& lo, float& hi) {
    asm("mov.b64 {%0,%1}, %2;" : "=f"(lo), "=f"(hi) : "l"(v));
}
__device__ __forceinline__ u64 fma2(u64 a, u64 b, u64 c) {
    u64 d; asm("fma.rn.f32x2 %0, %1, %2, %3;" : "=l"(d) : "l"(a), "l"(b), "l"(c)); return d;
}
__device__ __forceinline__ float fast_sin(float x)  { float r; asm("sin.approx.f32 %0, %1;"  : "=f"(r) : "f"(x)); return r; }
__device__ __forceinline__ float fast_cos(float x)  { float r; asm("cos.approx.f32 %0, %1;"  : "=f"(r) : "f"(x)); return r; }
__device__ __forceinline__ float fast_tanh(float x) { float r; asm("tanh.approx.f32 %0, %1;" : "=f"(r) : "f"(x)); return r; }

// Fused rank-12 outer product. B stored UN-duplicated in shared (3 LDS.128/mi
// instead of 6), lane duplication via ALU movs: cuts L1 wavefronts 10->7 per 512B.
//   out[m*NN + n] = c0*z0[m] + sum_{k=0..10} A[n,k] * B[m,k+1]
__global__ void __launch_bounds__(TPB, 4)
fused_kernel(const float* __restrict__ phi, const float* __restrict__ POD,
             const float* __restrict__ c, const float* __restrict__ omega,
             const float* __restrict__ z, const float* __restrict__ zsin,
             const float* __restrict__ zcos, const float* __restrict__ ztanh,
             const float* __restrict__ sc, const float* __restrict__ cc,
             const float* __restrict__ tc,
             float* __restrict__ out_final, float* __restrict__ out_latent,
             float* __restrict__ out_z) {
    __shared__ __align__(16) float Bs[MC_MAX * KB];  // plain floats, 48B per m

    const int tid = threadIdx.x;
    const int mBase = blockIdx.y * MC_MAX;            // y in [0,10); MC*MT == MM exactly

    // ---- B tile: threads 0..MC_MAX-1 compute one m row each ----
    if (tid < MC_MAX) {
        int m = mBase + tid;
        float* b = Bs + tid * KB;
        b[0] = c[0] * z[m];
#pragma unroll
        for (int t = 1; t < 6; t++) b[t] = z[t * MM + m];
        b[6]  = sc[0] * zsin[m];
        b[7]  = sc[1] * zsin[MM + m];
        b[8]  = cc[0] * zcos[m];
        b[9]  = cc[1] * zcos[MM + m];
        b[10] = tc[0] * ztanh[m];
        b[11] = tc[1] * ztanh[MM + m];
    }

    // ---- z_values copy (once, by block (0,0)) ----
    if (blockIdx.x == 0 && blockIdx.y == 0) {
        for (int i = tid; i < 6 * MM; i += TPB) out_z[i] = z[i];
    }
    __syncthreads();

    const int n0 = (blockIdx.x * TPB + tid) * VN;
    if (n0 >= NN) return;  // NN % 4 == 0; in-range threads write full float4

    // ---- A features inline for this thread's 4 n's ----
    float4 p0 = *(const float4*)(phi + n0);
    float4 p1 = *(const float4*)(phi + NN + n0);
    float4 qa = *(const float4*)(POD + 2 * n0);
    float4 qb = *(const float4*)(POD + 2 * n0 + 4);

    float y0[4], y1[4];
    y0[0] = p0.x * qa.x;  y1[0] = p1.x * qa.y;
    y0[1] = p0.y * qa.z;  y1[1] = p1.y * qa.w;
    y0[2] = p0.z * qb.x;  y1[2] = p1.z * qb.y;
    y0[3] = p0.w * qb.z;  y1[3] = p1.w * qb.w;

    if (blockIdx.y == 0) {  // latent_spatial (N,2): [y0, y1] interleaved
        *(float4*)(out_latent + 2 * n0)     = make_float4(y0[0], y1[0], y0[1], y1[1]);
        *(float4*)(out_latent + 2 * n0 + 4) = make_float4(y0[2], y1[2], y0[3], y1[3]);
    }

    float c1 = c[1], c2 = c[2], c3 = c[3], c4 = c[4], c5 = c[5];
    float w0 = omega[0], w1 = omega[1], w2 = omega[2];
    float w3 = omega[3], w4 = omega[4], w5 = omega[5];

    // Pack A features directly as f32x2 pairs (n0/n1 lane, n2/n3 lane).
    u64 pa01[KA], pa23[KA];
#define PACK_K(k, EXPR)                                                      \
    pa01[k] = pack2(EXPR(0), EXPR(1));                                       \
    pa23[k] = pack2(EXPR(2), EXPR(3));
#define F0(j)  (c1 * y0[j])
#define F1(j)  (c2 * y1[j])
#define F2(j)  (c3 * y0[j] * y0[j])
#define F3(j)  (c4 * y0[j] * y1[j])
#define F4(j)  (c5 * y1[j] * y1[j])
#define F5(j)  fast_sin(w0 * y0[j])
#define F6(j)  fast_sin(w3 * y1[j])
#define F7(j)  fast_cos(w1 * y0[j])
#define F8(j)  fast_cos(w4 * y1[j])
#define F9(j)  fast_tanh(w2 * y0[j])
#define F10(j) fast_tanh(w5 * y1[j])
    PACK_K(0, F0)  PACK_K(1, F1)  PACK_K(2, F2)  PACK_K(3, F3)
    PACK_K(4, F4)  PACK_K(5, F5)  PACK_K(6, F6)  PACK_K(7, F7)
    PACK_K(8, F8)  PACK_K(9, F9)  PACK_K(10, F10)

    // ---- main store stream ----
    float* outBase = out_final + (size_t)mBase * NN + n0;
#pragma unroll 4
    for (int mi = 0; mi < MC_MAX; ++mi) {
        const float4* bb = (const float4*)(Bs + mi * KB);  // 3x LDS.128 (broadcast)
        float4 q0 = bb[0];   // b0..b3
        float4 q1 = bb[1];   // b4..b7
        float4 q2 = bb[2];   // b8..b11

        u64 d0  = dup2(q0.x);                       // init = c0*z0[m]
        u64 d1  = dup2(q0.y);
        u64 acc01 = fma2(pa01[0], d1, d0);
        u64 acc23 = fma2(pa23[0], d1, d0);
        u64 d2  = dup2(q0.z);
        acc01 = fma2(pa01[1], d2, acc01);  acc23 = fma2(pa23[1], d2, acc23);
        u64 d3  = dup2(q0.w);
        acc01 = fma2(pa01[2], d3, acc01);  acc23 = fma2(pa23[2], d3, acc23);
        u64 d4  = dup2(q1.x);
        acc01 = fma2(pa01[3], d4, acc01);  acc23 = fma2(pa23[3], d4, acc23);
        u64 d5  = dup2(q1.y);
        acc01 = fma2(pa01[4], d5, acc01);  acc23 = fma2(pa23[4], d5, acc23);
        u64 d6  = dup2(q1.z);
        acc01 = fma2(pa01[5], d6, acc01);  acc23 = fma2(pa23[5], d6, acc23);
        u64 d7  = dup2(q1.w);
        acc01 = fma2(pa01[6], d7, acc01);  acc23 = fma2(pa23[6], d7, acc23);
        u64 d8  = dup2(q2.x);
        acc01 = fma2(pa01[7], d8, acc01);  acc23 = fma2(pa23[7], d8, acc23);
        u64 d9  = dup2(q2.y);
        acc01 = fma2(pa01[8], d9, acc01);  acc23 = fma2(pa23[8], d9, acc23);
        u64 d10 = dup2(q2.z);
        acc01 = fma2(pa01[9], d10, acc01); acc23 = fma2(pa23[9], d10, acc23);
        u64 d11 = dup2(q2.w);
        acc01 = fma2(pa01[10], d11, acc01); acc23 = fma2(pa23[10], d11, acc23);

        float4 o;
        unpack2(acc01, o.x, o.y);
        unpack2(acc23, o.z, o.w);
        __stcs((float4*)(outBase + (size_t)mi * NN), o);
    }
}

extern "C" void kernel_launch(void* const* d_in, const int* in_sizes, int n_in,
                              void* d_out, int out_size) {
    // Input order: X, phi, POD_modes, c_coef, z_values, zsin, zcos,
    //              ztanh, sin_coef, cos_coef, tanh_coef, omega
    const float* phi   = (const float*)d_in[1];
    const float* POD   = (const float*)d_in[2];
    const float* c     = (const float*)d_in[3];
    const float* z     = (const float*)d_in[4];
    const float* zsin  = (const float*)d_in[5];
    const float* zcos  = (const float*)d_in[6];
    const float* ztanh = (const float*)d_in[7];
    const float* sc    = (const float*)d_in[8];
    const float* cc    = (const float*)d_in[9];
    const float* tc    = (const float*)d_in[10];
    const float* omega = (const float*)d_in[11];

    float* out        = (float*)d_out;
    float* out_final  = out;                              // (M, N)
    float* out_latent = out + (size_t)MM * NN;            // (N, 2)
    float* out_z      = out_latent + (size_t)NN * 2;      // (6, M)

    dim3 grid((NN + TPB * VN - 1) / (TPB * VN), MT);      // (98, 10) = 980 blocks
    fused_kernel<<<grid, TPB>>>(phi, POD, c, omega, z, zsin, zcos, ztanh,
                                sc, cc, tc, out_final, out_latent, out_z);
}